// round 8
// baseline (speedup 1.0000x reference)
#include <cuda_runtime.h>
#include <math.h>

// Kalman filter one-step-ahead predictions. B=512, T=256, S=32, M=4.
// Warp-per-batch, register-resident symmetric P (lane j holds column j==row j).
// GEMM-A (X = P_u * F^T): packed fma.rn.f32x2 with broadcast LDS.128 of F.
// GEMM-B (P' = F * X + Q): scalar FFMA with F from __constant__ memory —
// warp-uniform immediate addresses, scalar consumer -> LDCU/UR path candidate,
// relieving the saturated shared-memory crossbar (L1 78.6% in R7).

#define Bn 512
#define Tn 256
#define Sn 32
#define Mn 4
#define XLD 34  // sX row stride in floats

using u64 = unsigned long long;

__device__ __forceinline__ u64 pack2(float lo, float hi) {
    u64 r; asm("mov.b64 %0,{%1,%2};" : "=l"(r) : "f"(lo), "f"(hi)); return r;
}
__device__ __forceinline__ void unpack2(u64 v, float& lo, float& hi) {
    asm("mov.b64 {%0,%1},%2;" : "=f"(lo), "=f"(hi) : "l"(v));
}
__device__ __forceinline__ u64 ffma2(u64 a, u64 b, u64 c) {
    u64 d; asm("fma.rn.f32x2 %0,%1,%2,%3;" : "=l"(d) : "l"(a), "l"(b), "l"(c)); return d;
}
__device__ __forceinline__ u64 fadd2(u64 a, u64 b) {
    u64 d; asm("add.rn.f32x2 %0,%1,%2;" : "=l"(d) : "l"(a), "l"(b)); return d;
}

// F columns in constant memory: cFcol[k*32 + i] = F[i][k]
__constant__ __align__(16) float cFcol[Sn * Sn];
__device__ __align__(16) float gStage[Sn * Sn];

__global__ void prep_kernel(const float* __restrict__ Fm)
{
    const int lane = threadIdx.x;
    for (int idx = lane; idx < Sn * Sn; idx += 32) {
        int i = idx >> 5, k = idx & 31;
        gStage[k * Sn + i] = Fm[i * Sn + k];
    }
}

__global__ __launch_bounds__(32) void kalman_kernel(
    const float* __restrict__ obs,       // [B,T,M]
    const float* __restrict__ Fm,        // [S,S]
    const float* __restrict__ Qm,        // [S,S]
    const float* __restrict__ Hm,        // [M,S]
    const float* __restrict__ Rm,        // [M,M]
    const float* __restrict__ init_mean, // [B,S]
    const float* __restrict__ init_cov,  // [B,S,S]
    float* __restrict__ out)
{
    const int b    = blockIdx.x;
    const int lane = threadIdx.x;

    // F column pairs (GEMM-A): fv[l*36+i] = F[i][l]
    __shared__ __align__(16) u64 sFTp[Sn * 18];
    // Q column pairs: [j*36+i] = Q[i][j]
    __shared__ __align__(16) u64 sQp[Sn * 18];
    // H per-l quads: [l*4+q] = H[q][l]
    __shared__ __align__(16) u64 sHTp[Sn * 2];
    // H row-major pairs: hr[q*34+l] = H[q][l]
    __shared__ __align__(16) u64 sHR[4 * 17];
    // F row-major pairs: fr[j*34+l] = F[j][l]  (mean predict, lane-varying)
    __shared__ __align__(16) u64 sFR[Sn * 17];
    // PH^T row-major: pht[r*34+l] = (P H^T)[l][r]
    __shared__ __align__(16) u64 sPHT[4 * 17];
    __shared__ __align__(16) float sX[Sn * XLD];
    __shared__ __align__(16) float sZ[Sn * 4];
    __shared__ __align__(16) u64 sMu[16];
    __shared__ __align__(16) u64 sMp[16];
    __shared__ float sR16[16];

    {
        float* fv  = (float*)sFTp;
        float* qv  = (float*)sQp;
        float* frf = (float*)sFR;
        for (int idx = lane; idx < Sn * Sn; idx += 32) {
            int i = idx >> 5, l = idx & 31;
            float f = Fm[idx];
            fv [l * 36 + i] = f;
            frf[i * 34 + l] = f;
            qv [l * 36 + i] = Qm[idx];
        }
        float* hv  = (float*)sHTp;
        float* hrf = (float*)sHR;
        for (int idx = lane; idx < Mn * Sn; idx += 32) {
            int q = idx >> 5, l = idx & 31;
            float h = Hm[idx];
            hv [l * 4 + q]  = h;
            hrf[q * 34 + l] = h;
        }
        if (lane < 16) sR16[lane] = Rm[lane];
    }

    float p[Sn];
#pragma unroll
    for (int i = 0; i < Sn; ++i)
        p[i] = init_cov[(size_t)b * (Sn * Sn) + i * Sn + lane];
    float mloc = init_mean[b * Sn + lane];

    float* muF = (float*)sMu;
    float* mpF = (float*)sMp;
    mpF[lane] = mloc;
    __syncwarp();

    const float* yb = obs + (size_t)b * (Tn * Mn);
    float* out_means = out;
    float* out_covs  = out + (size_t)Tn * Bn * Mn;

    float4 yn = *(const float4*)yb;
    float* phtF = (float*)sPHT;

#pragma unroll 1
    for (int t = 0; t < Tn; ++t) {
        float4 yv = yn;
        int tnext = (t + 1 < Tn) ? (t + 1) : (Tn - 1);
        yn = *(const float4*)(yb + 4 * tnext);

        // ---- mm[q] on lane q (q<4): dot(H row q, m_p)
        float mmv = 0.f;
        {
            u64 accm0 = 0ull, accm1 = 0ull;
            const u64* hq = &sHR[(lane & 3) * 17];
#pragma unroll
            for (int c = 0; c < 8; ++c) {
                accm0 = ffma2(hq[2 * c + 0], sMp[2 * c + 0], accm0);
                accm1 = ffma2(hq[2 * c + 1], sMp[2 * c + 1], accm1);
            }
            u64 accm = fadd2(accm0, accm1);
            float alo, ahi; unpack2(accm, alo, ahi);
            mmv = alo + ahi;
        }

        // ---- phtt = row `lane` of P*H^T (4 split chains)
        u64 a00 = 0ull, a01 = 0ull, a10 = 0ull, a11 = 0ull;
#pragma unroll
        for (int l = 0; l < Sn; l += 2) {
            ulonglong2 h0 = *(const ulonglong2*)&sHTp[l * 2];
            ulonglong2 h1 = *(const ulonglong2*)&sHTp[(l + 1) * 2];
            u64 ps0 = pack2(p[l], p[l]);
            u64 ps1 = pack2(p[l + 1], p[l + 1]);
            a00 = ffma2(ps0, h0.x, a00); a10 = ffma2(ps0, h0.y, a10);
            a01 = ffma2(ps1, h1.x, a01); a11 = ffma2(ps1, h1.y, a11);
        }
        u64 ph2a = fadd2(a00, a01);
        u64 ph2b = fadd2(a10, a11);
        float ph0, ph1, phh2, ph3;
        unpack2(ph2a, ph0, ph1);
        unpack2(ph2b, phh2, ph3);
        phtF[0 * 34 + lane] = ph0;
        phtF[1 * 34 + lane] = ph1;
        phtF[2 * 34 + lane] = phh2;
        phtF[3 * 34 + lane] = ph3;

        float c0 = __shfl_sync(0xffffffffu, mmv, 0);
        float c1 = __shfl_sync(0xffffffffu, mmv, 1);
        float c2 = __shfl_sync(0xffffffffu, mmv, 2);
        float c3 = __shfl_sync(0xffffffffu, mmv, 3);
        if (lane == 0)
            *(float4*)&out_means[((size_t)t * Bn + b) * 4] = make_float4(c0, c1, c2, c3);
        float r0 = yv.x - c0, r1 = yv.y - c1, r2 = yv.z - c2, r3 = yv.w - c3;
        __syncwarp();

        // ---- S = H*(PH^T) + R
        int q = (lane >> 2) & 3, r = lane & 3;
        float sv;
        {
            u64 acc0 = 0ull, acc1 = 0ull;
            const u64* hq = &sHR [q * 17];
            const u64* pr = &sPHT[r * 17];
#pragma unroll
            for (int c = 0; c < 8; ++c) {
                acc0 = ffma2(hq[2 * c + 0], pr[2 * c + 0], acc0);
                acc1 = ffma2(hq[2 * c + 1], pr[2 * c + 1], acc1);
            }
            u64 acc = fadd2(acc0, acc1);
            float alo, ahi; unpack2(acc, alo, ahi);
            sv = sR16[(q << 2) | r] + (alo + ahi);
        }
        if (lane < 16)
            out_covs[((size_t)t * Bn + b) * 16 + lane] = sv;

        if (t == Tn - 1) break;

        // ---- broadcast S, rsqrt 4x4 Cholesky (redundant per lane)
        float s00 = __shfl_sync(0xffffffffu, sv, 0);
        float s10 = __shfl_sync(0xffffffffu, sv, 4);
        float s11 = __shfl_sync(0xffffffffu, sv, 5);
        float s20 = __shfl_sync(0xffffffffu, sv, 8);
        float s21 = __shfl_sync(0xffffffffu, sv, 9);
        float s22 = __shfl_sync(0xffffffffu, sv, 10);
        float s30 = __shfl_sync(0xffffffffu, sv, 12);
        float s31 = __shfl_sync(0xffffffffu, sv, 13);
        float s32 = __shfl_sync(0xffffffffu, sv, 14);
        float s33 = __shfl_sync(0xffffffffu, sv, 15);
        float i0 = rsqrtf(s00);
        float L10 = s10 * i0, L20 = s20 * i0, L30 = s30 * i0;
        float i1 = rsqrtf(s11 - L10 * L10);
        float L21 = (s21 - L20 * L10) * i1;
        float L31 = (s31 - L30 * L10) * i1;
        float i2 = rsqrtf(s22 - L20 * L20 - L21 * L21);
        float L32 = (s32 - L30 * L20 - L31 * L21) * i2;
        float i3 = rsqrtf(s33 - L30 * L30 - L31 * L31 - L32 * L32);

        float z0 = ph0 * i0;
        float z1 = (ph1 - L10 * z0) * i1;
        float z2 = (phh2 - L20 * z0 - L21 * z1) * i2;
        float z3 = (ph3 - L30 * z0 - L31 * z1 - L32 * z2) * i3;
        float k3 = z3 * i3;
        float k2 = (z2 - L32 * k3) * i2;
        float k1 = (z1 - L21 * k2 - L31 * k3) * i1;
        float k0 = (z0 - L10 * k1 - L20 * k2 - L30 * k3) * i0;

        *(float4*)&sZ[lane * 4] = make_float4(z0, z1, z2, z3);
        __syncwarp();

        mloc = fmaf(k0, r0, fmaf(k1, r1, fmaf(k2, r2, fmaf(k3, r3, mloc))));
        muF[lane] = mloc;

        // ---- symmetric rank-4 downdate
#pragma unroll
        for (int i = 0; i < Sn; ++i) {
            float4 zi = *(const float4*)&sZ[i * 4];
            float d = zi.x * z0;
            d = fmaf(zi.y, z1, d);
            d = fmaf(zi.z, z2, d);
            d = fmaf(zi.w, z3, d);
            p[i] -= d;
        }

        // ---- GEMM-A: X row `lane` = p . F^T  (FFMA2, shared F)
        u64 x2[16];
#pragma unroll
        for (int c = 0; c < 16; ++c) x2[c] = 0ull;
#pragma unroll
        for (int l = 0; l < Sn; ++l) {
            u64 ps = pack2(p[l], p[l]);
            const ulonglong2* fr = (const ulonglong2*)&sFTp[l * 18];
#pragma unroll
            for (int c2 = 0; c2 < 8; ++c2) {
                ulonglong2 f = fr[c2];
                x2[2 * c2 + 0] = ffma2(ps, f.x, x2[2 * c2 + 0]);
                x2[2 * c2 + 1] = ffma2(ps, f.y, x2[2 * c2 + 1]);
            }
        }
#pragma unroll
        for (int c = 0; c < 16; ++c)
            *(u64*)&sX[lane * XLD + 2 * c] = x2[c];
        __syncwarp();

        // ---- mean predict (shared F rows, lane-varying)
        float mp;
        {
            u64 acc0 = 0ull, acc1 = 0ull;
            const u64* frw = &sFR[lane * 17];
#pragma unroll
            for (int c = 0; c < 8; ++c) {
                acc0 = ffma2(frw[2 * c + 0], sMu[2 * c + 0], acc0);
                acc1 = ffma2(frw[2 * c + 1], sMu[2 * c + 1], acc1);
            }
            u64 acc = fadd2(acc0, acc1);
            float alo, ahi; unpack2(acc, alo, ahi);
            mp = alo + ahi;
        }

        // ---- GEMM-B: P' col `lane` = F * X[:,lane] + Q[:,lane]
        //      scalar FFMA, F from __constant__ (uniform immediate addresses)
        {
            float a[Sn];
            const ulonglong2* qr = (const ulonglong2*)&sQp[lane * 18];
#pragma unroll
            for (int c2 = 0; c2 < 8; ++c2) {
                ulonglong2 qq = qr[c2];
                unpack2(qq.x, a[4 * c2 + 0], a[4 * c2 + 1]);
                unpack2(qq.y, a[4 * c2 + 2], a[4 * c2 + 3]);
            }
#pragma unroll
            for (int k = 0; k < Sn; ++k) {
                float xv = sX[k * XLD + lane];
#pragma unroll
                for (int i = 0; i < Sn; ++i)
                    a[i] = fmaf(xv, cFcol[k * Sn + i], a[i]);
            }
#pragma unroll
            for (int i = 0; i < Sn; ++i) p[i] = a[i];
        }

        mloc = mp;
        mpF[lane] = mp;
        __syncwarp();
    }
}

extern "C" void kernel_launch(void* const* d_in, const int* in_sizes, int n_in,
                              void* d_out, int out_size)
{
    const float* obs       = (const float*)d_in[0];
    const float* Fm        = (const float*)d_in[1];
    const float* Qm        = (const float*)d_in[2];
    const float* Hm        = (const float*)d_in[3];
    const float* Rm        = (const float*)d_in[4];
    const float* init_mean = (const float*)d_in[5];
    const float* init_cov  = (const float*)d_in[6];
    float* out = (float*)d_out;

    prep_kernel<<<1, 32>>>(Fm);

    void* stage = nullptr;
    cudaGetSymbolAddress(&stage, gStage);
    cudaMemcpyToSymbolAsync(cFcol, stage, Sn * Sn * sizeof(float), 0,
                            cudaMemcpyDeviceToDevice, 0);

    kalman_kernel<<<Bn, 32>>>(obs, Fm, Qm, Hm, Rm, init_mean, init_cov, out);
}

// round 9
// speedup vs baseline: 1.1409x; 1.1409x over previous
#include <cuda_runtime.h>
#include <math.h>

// Kalman filter one-step-ahead predictions. B=512, T=256, S=32, M=4.
// TWO warps per batch (512 blocks x 64 threads): each warp computes one
// 16-wide output half of the two 32x32 GEMMs (halving its F broadcast stream),
// doubling warp-level parallelism against the saturated L1/shared crossbar.
// Serial filter math (Cholesky, solves, downdate) runs redundantly in both
// warps on identical register state (bitwise-deterministic). Two
// __syncthreads() per step: X hand-off and P' half-exchange.

#define Bn 512
#define Tn 256
#define Sn 32
#define Mn 4
#define XLD 34  // sX row stride in floats
#define PLD 33  // sPn row stride in floats (conflict-free exchange)

using u64 = unsigned long long;

__device__ __forceinline__ u64 pack2(float lo, float hi) {
    u64 r; asm("mov.b64 %0,{%1,%2};" : "=l"(r) : "f"(lo), "f"(hi)); return r;
}
__device__ __forceinline__ void unpack2(u64 v, float& lo, float& hi) {
    asm("mov.b64 {%0,%1},%2;" : "=f"(lo), "=f"(hi) : "l"(v));
}
__device__ __forceinline__ u64 ffma2(u64 a, u64 b, u64 c) {
    u64 d; asm("fma.rn.f32x2 %0,%1,%2,%3;" : "=l"(d) : "l"(a), "l"(b), "l"(c)); return d;
}
__device__ __forceinline__ u64 fadd2(u64 a, u64 b) {
    u64 d; asm("add.rn.f32x2 %0,%1,%2;" : "=l"(d) : "l"(a), "l"(b)); return d;
}

__global__ __launch_bounds__(64) void kalman_kernel(
    const float* __restrict__ obs,       // [B,T,M]
    const float* __restrict__ Fm,        // [S,S]
    const float* __restrict__ Qm,        // [S,S]
    const float* __restrict__ Hm,        // [M,S]
    const float* __restrict__ Rm,        // [M,M]
    const float* __restrict__ init_mean, // [B,S]
    const float* __restrict__ init_cov,  // [B,S,S]
    float* __restrict__ out)
{
    const int b    = blockIdx.x;
    const int tid  = threadIdx.x;
    const int wid  = tid >> 5;          // 0 or 1
    const int lane = tid & 31;
    const int half  = wid << 4;         // float/row offset of this warp's half
    const int halfu = wid << 3;         // u64 offset of this warp's half

    // F column pairs: fv[l*36+i] = F[i][l]
    __shared__ __align__(16) u64 sFTp[Sn * 18];
    // Q column pairs: [j*36+i] = Q[i][j]
    __shared__ __align__(16) u64 sQp[Sn * 18];
    // H per-l quads: [l*4+q] = H[q][l]
    __shared__ __align__(16) u64 sHTp[Sn * 2];
    // H row-major pairs: hr[q*34+l] = H[q][l]
    __shared__ __align__(16) u64 sHR[4 * 17];
    // F row-major pairs: fr[j*34+l] = F[j][l]  (mean predict)
    __shared__ __align__(16) u64 sFR[Sn * 17];
    // PH^T row-major: pht[r*34+l] = (P H^T)[l][r]
    __shared__ __align__(16) u64 sPHT[4 * 17];
    // X = P_u * F^T rows, stride 34
    __shared__ __align__(16) float sX[Sn * XLD];
    // whitened z per row
    __shared__ __align__(16) float sZ[Sn * 4];
    // P' exchange buffer: sPn[i*33 + j] = P'[i][j]
    __shared__ __align__(16) float sPn[Sn * PLD];
    __shared__ __align__(16) u64 sMu[16];
    __shared__ __align__(16) u64 sMp[16];
    __shared__ float sR16[16];

    {
        float* fv  = (float*)sFTp;
        float* qv  = (float*)sQp;
        float* frf = (float*)sFR;
        for (int idx = tid; idx < Sn * Sn; idx += 64) {
            int i = idx >> 5, l = idx & 31;
            float f = Fm[idx];
            fv [l * 36 + i] = f;
            frf[i * 34 + l] = f;
            qv [l * 36 + i] = Qm[idx];
        }
        float* hv  = (float*)sHTp;
        float* hrf = (float*)sHR;
        for (int idx = tid; idx < Mn * Sn; idx += 64) {
            int q = idx >> 5, l = idx & 31;
            float h = Hm[idx];
            hv [l * 4 + q]  = h;
            hrf[q * 34 + l] = h;
        }
        if (tid < 16) sR16[tid] = Rm[tid];
    }

    // per-lane state (replicated in both warps): P column `lane`, mean elem
    float p[Sn];
#pragma unroll
    for (int i = 0; i < Sn; ++i)
        p[i] = init_cov[(size_t)b * (Sn * Sn) + i * Sn + lane];
    float mloc = init_mean[b * Sn + lane];

    float* muF = (float*)sMu;
    float* mpF = (float*)sMp;
    if (wid == 0) mpF[lane] = mloc;
    __syncthreads();

    const float* yb = obs + (size_t)b * (Tn * Mn);
    float* out_means = out;
    float* out_covs  = out + (size_t)Tn * Bn * Mn;

    float4 yn = *(const float4*)yb;
    float* phtF = (float*)sPHT;

#pragma unroll 1
    for (int t = 0; t < Tn; ++t) {
        float4 yv = yn;
        int tnext = (t + 1 < Tn) ? (t + 1) : (Tn - 1);
        yn = *(const float4*)(yb + 4 * tnext);

        // ---- mm[q] on lane q (q<4): dot(H row q, m_p)   [redundant per warp]
        float mmv = 0.f;
        {
            u64 accm0 = 0ull, accm1 = 0ull;
            const u64* hq = &sHR[(lane & 3) * 17];
#pragma unroll
            for (int c = 0; c < 8; ++c) {
                accm0 = ffma2(hq[2 * c + 0], sMp[2 * c + 0], accm0);
                accm1 = ffma2(hq[2 * c + 1], sMp[2 * c + 1], accm1);
            }
            u64 accm = fadd2(accm0, accm1);
            float alo, ahi; unpack2(accm, alo, ahi);
            mmv = alo + ahi;
        }

        // ---- phtt = row `lane` of P*H^T (4 split chains)  [redundant]
        u64 a00 = 0ull, a01 = 0ull, a10 = 0ull, a11 = 0ull;
#pragma unroll
        for (int l = 0; l < Sn; l += 2) {
            ulonglong2 h0 = *(const ulonglong2*)&sHTp[l * 2];
            ulonglong2 h1 = *(const ulonglong2*)&sHTp[(l + 1) * 2];
            u64 ps0 = pack2(p[l], p[l]);
            u64 ps1 = pack2(p[l + 1], p[l + 1]);
            a00 = ffma2(ps0, h0.x, a00); a10 = ffma2(ps0, h0.y, a10);
            a01 = ffma2(ps1, h1.x, a01); a11 = ffma2(ps1, h1.y, a11);
        }
        u64 ph2a = fadd2(a00, a01);
        u64 ph2b = fadd2(a10, a11);
        float ph0, ph1, phh2, ph3;
        unpack2(ph2a, ph0, ph1);
        unpack2(ph2b, phh2, ph3);
        // both warps write identical values (deterministic from identical state)
        phtF[0 * 34 + lane] = ph0;
        phtF[1 * 34 + lane] = ph1;
        phtF[2 * 34 + lane] = phh2;
        phtF[3 * 34 + lane] = ph3;

        float c0 = __shfl_sync(0xffffffffu, mmv, 0);
        float c1 = __shfl_sync(0xffffffffu, mmv, 1);
        float c2 = __shfl_sync(0xffffffffu, mmv, 2);
        float c3 = __shfl_sync(0xffffffffu, mmv, 3);
        if (tid == 0)
            *(float4*)&out_means[((size_t)t * Bn + b) * 4] = make_float4(c0, c1, c2, c3);
        float r0 = yv.x - c0, r1 = yv.y - c1, r2 = yv.z - c2, r3 = yv.w - c3;
        __syncwarp();

        // ---- S = H*(PH^T) + R   [redundant; only warp 0 stores]
        int q = (lane >> 2) & 3, r = lane & 3;
        float sv;
        {
            u64 acc0 = 0ull, acc1 = 0ull;
            const u64* hq = &sHR [q * 17];
            const u64* pr = &sPHT[r * 17];
#pragma unroll
            for (int c = 0; c < 8; ++c) {
                acc0 = ffma2(hq[2 * c + 0], pr[2 * c + 0], acc0);
                acc1 = ffma2(hq[2 * c + 1], pr[2 * c + 1], acc1);
            }
            u64 acc = fadd2(acc0, acc1);
            float alo, ahi; unpack2(acc, alo, ahi);
            sv = sR16[(q << 2) | r] + (alo + ahi);
        }
        if (wid == 0 && lane < 16)
            out_covs[((size_t)t * Bn + b) * 16 + lane] = sv;

        if (t == Tn - 1) break;

        // ---- broadcast S, rsqrt 4x4 Cholesky (redundant per lane & warp)
        float s00 = __shfl_sync(0xffffffffu, sv, 0);
        float s10 = __shfl_sync(0xffffffffu, sv, 4);
        float s11 = __shfl_sync(0xffffffffu, sv, 5);
        float s20 = __shfl_sync(0xffffffffu, sv, 8);
        float s21 = __shfl_sync(0xffffffffu, sv, 9);
        float s22 = __shfl_sync(0xffffffffu, sv, 10);
        float s30 = __shfl_sync(0xffffffffu, sv, 12);
        float s31 = __shfl_sync(0xffffffffu, sv, 13);
        float s32 = __shfl_sync(0xffffffffu, sv, 14);
        float s33 = __shfl_sync(0xffffffffu, sv, 15);
        float i0 = rsqrtf(s00);
        float L10 = s10 * i0, L20 = s20 * i0, L30 = s30 * i0;
        float i1 = rsqrtf(s11 - L10 * L10);
        float L21 = (s21 - L20 * L10) * i1;
        float L31 = (s31 - L30 * L10) * i1;
        float i2 = rsqrtf(s22 - L20 * L20 - L21 * L21);
        float L32 = (s32 - L30 * L20 - L31 * L21) * i2;
        float i3 = rsqrtf(s33 - L30 * L30 - L31 * L31 - L32 * L32);

        float z0 = ph0 * i0;
        float z1 = (ph1 - L10 * z0) * i1;
        float z2 = (phh2 - L20 * z0 - L21 * z1) * i2;
        float z3 = (ph3 - L30 * z0 - L31 * z1 - L32 * z2) * i3;
        float k3 = z3 * i3;
        float k2 = (z2 - L32 * k3) * i2;
        float k1 = (z1 - L21 * k2 - L31 * k3) * i1;
        float k0 = (z0 - L10 * k1 - L20 * k2 - L30 * k3) * i0;

        *(float4*)&sZ[lane * 4] = make_float4(z0, z1, z2, z3);  // identical both warps
        __syncwarp();

        mloc = fmaf(k0, r0, fmaf(k1, r1, fmaf(k2, r2, fmaf(k3, r3, mloc))));
        muF[lane] = mloc;  // identical both warps

        // ---- symmetric rank-4 downdate  [redundant]
#pragma unroll
        for (int i = 0; i < Sn; ++i) {
            float4 zi = *(const float4*)&sZ[i * 4];
            float d = zi.x * z0;
            d = fmaf(zi.y, z1, d);
            d = fmaf(zi.z, z2, d);
            d = fmaf(zi.w, z3, d);
            p[i] -= d;
        }

        // ---- GEMM-A (half): X[lane][m], m in [half, half+16)
        u64 x2[8];
#pragma unroll
        for (int c = 0; c < 8; ++c) x2[c] = 0ull;
#pragma unroll
        for (int l = 0; l < Sn; ++l) {
            u64 ps = pack2(p[l], p[l]);
            const ulonglong2* fr = (const ulonglong2*)&sFTp[l * 18 + halfu];
#pragma unroll
            for (int c2 = 0; c2 < 4; ++c2) {
                ulonglong2 f = fr[c2];
                x2[2 * c2 + 0] = ffma2(ps, f.x, x2[2 * c2 + 0]);
                x2[2 * c2 + 1] = ffma2(ps, f.y, x2[2 * c2 + 1]);
            }
        }
#pragma unroll
        for (int c = 0; c < 8; ++c)
            *(u64*)&sX[lane * XLD + half + 2 * c] = x2[c];

        __syncthreads();   // BAR1: X halves complete

        // ---- mean predict  [redundant]
        float mp;
        {
            u64 acc0 = 0ull, acc1 = 0ull;
            const u64* frw = &sFR[lane * 17];
#pragma unroll
            for (int c = 0; c < 8; ++c) {
                acc0 = ffma2(frw[2 * c + 0], sMu[2 * c + 0], acc0);
                acc1 = ffma2(frw[2 * c + 1], sMu[2 * c + 1], acc1);
            }
            u64 acc = fadd2(acc0, acc1);
            float alo, ahi; unpack2(acc, alo, ahi);
            mp = alo + ahi;
        }

        // ---- GEMM-B (half): P'[i][lane] for i in [half, half+16)
        float tmp[16];
        {
            u64 a2[8];
            const ulonglong2* qr = (const ulonglong2*)&sQp[lane * 18 + halfu];
#pragma unroll
            for (int c2 = 0; c2 < 4; ++c2) {
                ulonglong2 qq = qr[c2];
                a2[2 * c2 + 0] = qq.x;
                a2[2 * c2 + 1] = qq.y;
            }
#pragma unroll 8
            for (int k = 0; k < Sn; ++k) {
                float xv = sX[k * XLD + lane];
                u64 xs = pack2(xv, xv);
                const ulonglong2* fr = (const ulonglong2*)&sFTp[k * 18 + halfu];
#pragma unroll
                for (int c2 = 0; c2 < 4; ++c2) {
                    ulonglong2 f = fr[c2];
                    a2[2 * c2 + 0] = ffma2(xs, f.x, a2[2 * c2 + 0]);
                    a2[2 * c2 + 1] = ffma2(xs, f.y, a2[2 * c2 + 1]);
                }
            }
#pragma unroll
            for (int c = 0; c < 8; ++c)
                unpack2(a2[c], tmp[2 * c], tmp[2 * c + 1]);
        }

        // publish own half of P' column `lane`
#pragma unroll
        for (int rr = 0; rr < 16; ++rr)
            sPn[(half + rr) * PLD + lane] = tmp[rr];
        mloc = mp;
        mpF[lane] = mp;   // identical both warps

        __syncthreads();   // BAR2: P' halves complete

        // ---- reassemble full P column: own half from regs, other from shared
        const int other = half ^ 16;
#pragma unroll
        for (int rr = 0; rr < 16; ++rr) p[half + rr] = tmp[rr];
#pragma unroll
        for (int rr = 0; rr < 16; ++rr)
            p[other + rr] = sPn[(other + rr) * PLD + lane];
    }
}

extern "C" void kernel_launch(void* const* d_in, const int* in_sizes, int n_in,
                              void* d_out, int out_size)
{
    const float* obs       = (const float*)d_in[0];
    const float* Fm        = (const float*)d_in[1];
    const float* Qm        = (const float*)d_in[2];
    const float* Hm        = (const float*)d_in[3];
    const float* Rm        = (const float*)d_in[4];
    const float* init_mean = (const float*)d_in[5];
    const float* init_cov  = (const float*)d_in[6];
    float* out = (float*)d_out;

    kalman_kernel<<<Bn, 64>>>(obs, Fm, Qm, Hm, Rm, init_mean, init_cov, out);
}

// round 10
// speedup vs baseline: 1.2962x; 1.1362x over previous
#include <cuda_runtime.h>
#include <math.h>

// Kalman filter one-step-ahead predictions. B=512, T=256, S=32, M=4.
// Warp-per-batch (32-thread blocks x 512), register-resident symmetric P.
// R10 = R7 + LDS bank-conflict elimination:
//   * Q column held in registers (loop-invariant)  [-128 wf/step]
//   * X round-trip buffer scalar, stride 33 (odd -> conflict-free stores)
//   * mean-predict F rows in a scalar stride-33 plane
// GEMM F operand remains broadcast LDS.128 (irreducible uniform stream).

#define Bn 512
#define Tn 256
#define Sn 32
#define Mn 4
#define XS 33   // scalar stride for X and F-row planes (odd => conflict-free)

using u64 = unsigned long long;

__device__ __forceinline__ u64 pack2(float lo, float hi) {
    u64 r; asm("mov.b64 %0,{%1,%2};" : "=l"(r) : "f"(lo), "f"(hi)); return r;
}
__device__ __forceinline__ void unpack2(u64 v, float& lo, float& hi) {
    asm("mov.b64 {%0,%1},%2;" : "=f"(lo), "=f"(hi) : "l"(v));
}
__device__ __forceinline__ u64 ffma2(u64 a, u64 b, u64 c) {
    u64 d; asm("fma.rn.f32x2 %0,%1,%2,%3;" : "=l"(d) : "l"(a), "l"(b), "l"(c)); return d;
}
__device__ __forceinline__ u64 fadd2(u64 a, u64 b) {
    u64 d; asm("add.rn.f32x2 %0,%1,%2;" : "=l"(d) : "l"(a), "l"(b)); return d;
}

__global__ __launch_bounds__(32) void kalman_kernel(
    const float* __restrict__ obs,       // [B,T,M]
    const float* __restrict__ Fm,        // [S,S]
    const float* __restrict__ Qm,        // [S,S]
    const float* __restrict__ Hm,        // [M,S]
    const float* __restrict__ Rm,        // [M,M]
    const float* __restrict__ init_mean, // [B,S]
    const float* __restrict__ init_cov,  // [B,S,S]
    float* __restrict__ out)
{
    const int b    = blockIdx.x;
    const int lane = threadIdx.x;

    // F column pairs for GEMMs: fv[l*36+i] = F[i][l]  (broadcast LDS.128)
    __shared__ __align__(16) u64 sFTp[Sn * 18];
    // H per-l quads: [l*4+q] = H[q][l]  (PH GEMM broadcasts)
    __shared__ __align__(16) u64 sHTp[Sn * 2];
    // H row-major pairs: hr[q*34+l] = H[q][l]  (mm & S dots; bank-spread OK)
    __shared__ __align__(16) u64 sHR[4 * 17];
    // F rows, scalar plane: sFRs[j*33 + l] = F[j][l]  (mean predict)
    __shared__ float sFRs[Sn * XS];
    // PH^T row-major pairs: pht[r*34+l] = (P H^T)[l][r]
    __shared__ __align__(16) u64 sPHT[4 * 17];
    // X = P_u * F^T, scalar, row stride 33
    __shared__ float sX[Sn * XS];
    // whitened z per row
    __shared__ __align__(16) float sZ[Sn * 4];
    // updated mean pairs (mean predict) / predicted mean pairs (mm dot)
    __shared__ __align__(16) u64 sMu[16];
    __shared__ __align__(16) u64 sMp[16];
    __shared__ float sR16[16];

    {
        float* fv = (float*)sFTp;
        for (int idx = lane; idx < Sn * Sn; idx += 32) {
            int i = idx >> 5, l = idx & 31;
            float f = Fm[idx];
            fv  [l * 36 + i] = f;
            sFRs[i * XS + l] = f;
        }
        float* hv  = (float*)sHTp;
        float* hrf = (float*)sHR;
        for (int idx = lane; idx < Mn * Sn; idx += 32) {
            int q = idx >> 5, l = idx & 31;
            float h = Hm[idx];
            hv [l * 4 + q]  = h;
            hrf[q * 34 + l] = h;
        }
        if (lane < 16) sR16[lane] = Rm[lane];
    }

    // per-lane state: P column `lane` (== row, symmetric), Q column, mean elem
    float p[Sn];
#pragma unroll
    for (int i = 0; i < Sn; ++i)
        p[i] = init_cov[(size_t)b * (Sn * Sn) + i * Sn + lane];
    u64 q2[16];  // Q column pairs, loop-invariant (Q symmetric: col == row)
#pragma unroll
    for (int c = 0; c < 16; ++c)
        q2[c] = pack2(Qm[(2 * c) * Sn + lane], Qm[(2 * c + 1) * Sn + lane]);
    float mloc = init_mean[b * Sn + lane];

    float* muF = (float*)sMu;
    float* mpF = (float*)sMp;
    mpF[lane] = mloc;
    __syncwarp();

    const float* yb = obs + (size_t)b * (Tn * Mn);
    float* out_means = out;
    float* out_covs  = out + (size_t)Tn * Bn * Mn;

    float4 yn = *(const float4*)yb;
    float* phtF = (float*)sPHT;

#pragma unroll 1
    for (int t = 0; t < Tn; ++t) {
        float4 yv = yn;
        int tnext = (t + 1 < Tn) ? (t + 1) : (Tn - 1);
        yn = *(const float4*)(yb + 4 * tnext);

        // ---- mm[q] on lane q (q<4): dot(H row q, m_p)
        float mmv = 0.f;
        {
            u64 accm0 = 0ull, accm1 = 0ull;
            const u64* hq = &sHR[(lane & 3) * 17];
#pragma unroll
            for (int c = 0; c < 8; ++c) {
                accm0 = ffma2(hq[2 * c + 0], sMp[2 * c + 0], accm0);
                accm1 = ffma2(hq[2 * c + 1], sMp[2 * c + 1], accm1);
            }
            u64 accm = fadd2(accm0, accm1);
            float alo, ahi; unpack2(accm, alo, ahi);
            mmv = alo + ahi;
        }

        // ---- phtt = row `lane` of P*H^T (4 split chains)
        u64 a00 = 0ull, a01 = 0ull, a10 = 0ull, a11 = 0ull;
#pragma unroll
        for (int l = 0; l < Sn; l += 2) {
            ulonglong2 h0 = *(const ulonglong2*)&sHTp[l * 2];
            ulonglong2 h1 = *(const ulonglong2*)&sHTp[(l + 1) * 2];
            u64 ps0 = pack2(p[l], p[l]);
            u64 ps1 = pack2(p[l + 1], p[l + 1]);
            a00 = ffma2(ps0, h0.x, a00); a10 = ffma2(ps0, h0.y, a10);
            a01 = ffma2(ps1, h1.x, a01); a11 = ffma2(ps1, h1.y, a11);
        }
        u64 ph2a = fadd2(a00, a01);
        u64 ph2b = fadd2(a10, a11);
        float ph0, ph1, phh2, ph3;
        unpack2(ph2a, ph0, ph1);
        unpack2(ph2b, phh2, ph3);
        phtF[0 * 34 + lane] = ph0;
        phtF[1 * 34 + lane] = ph1;
        phtF[2 * 34 + lane] = phh2;
        phtF[3 * 34 + lane] = ph3;

        float c0 = __shfl_sync(0xffffffffu, mmv, 0);
        float c1 = __shfl_sync(0xffffffffu, mmv, 1);
        float c2 = __shfl_sync(0xffffffffu, mmv, 2);
        float c3 = __shfl_sync(0xffffffffu, mmv, 3);
        if (lane == 0)
            *(float4*)&out_means[((size_t)t * Bn + b) * 4] = make_float4(c0, c1, c2, c3);
        float r0 = yv.x - c0, r1 = yv.y - c1, r2 = yv.z - c2, r3 = yv.w - c3;
        __syncwarp();

        // ---- S = H*(PH^T) + R : lane (q,r), dup for lanes>=16 (bank-spread OK)
        int q = (lane >> 2) & 3, r = lane & 3;
        float sv;
        {
            u64 acc0 = 0ull, acc1 = 0ull;
            const u64* hq = &sHR [q * 17];
            const u64* pr = &sPHT[r * 17];
#pragma unroll
            for (int c = 0; c < 8; ++c) {
                acc0 = ffma2(hq[2 * c + 0], pr[2 * c + 0], acc0);
                acc1 = ffma2(hq[2 * c + 1], pr[2 * c + 1], acc1);
            }
            u64 acc = fadd2(acc0, acc1);
            float alo, ahi; unpack2(acc, alo, ahi);
            sv = sR16[(q << 2) | r] + (alo + ahi);
        }
        if (lane < 16)
            out_covs[((size_t)t * Bn + b) * 16 + lane] = sv;

        if (t == Tn - 1) break;

        // ---- broadcast S, rsqrt 4x4 Cholesky (redundant per lane)
        float s00 = __shfl_sync(0xffffffffu, sv, 0);
        float s10 = __shfl_sync(0xffffffffu, sv, 4);
        float s11 = __shfl_sync(0xffffffffu, sv, 5);
        float s20 = __shfl_sync(0xffffffffu, sv, 8);
        float s21 = __shfl_sync(0xffffffffu, sv, 9);
        float s22 = __shfl_sync(0xffffffffu, sv, 10);
        float s30 = __shfl_sync(0xffffffffu, sv, 12);
        float s31 = __shfl_sync(0xffffffffu, sv, 13);
        float s32 = __shfl_sync(0xffffffffu, sv, 14);
        float s33 = __shfl_sync(0xffffffffu, sv, 15);
        float i0 = rsqrtf(s00);
        float L10 = s10 * i0, L20 = s20 * i0, L30 = s30 * i0;
        float i1 = rsqrtf(s11 - L10 * L10);
        float L21 = (s21 - L20 * L10) * i1;
        float L31 = (s31 - L30 * L10) * i1;
        float i2 = rsqrtf(s22 - L20 * L20 - L21 * L21);
        float L32 = (s32 - L30 * L20 - L31 * L21) * i2;
        float i3 = rsqrtf(s33 - L30 * L30 - L31 * L31 - L32 * L32);

        // ---- whitened z (forward) and gain row (back solve)
        float z0 = ph0 * i0;
        float z1 = (ph1 - L10 * z0) * i1;
        float z2 = (phh2 - L20 * z0 - L21 * z1) * i2;
        float z3 = (ph3 - L30 * z0 - L31 * z1 - L32 * z2) * i3;
        float k3 = z3 * i3;
        float k2 = (z2 - L32 * k3) * i2;
        float k1 = (z1 - L21 * k2 - L31 * k3) * i1;
        float k0 = (z0 - L10 * k1 - L20 * k2 - L30 * k3) * i0;

        *(float4*)&sZ[lane * 4] = make_float4(z0, z1, z2, z3);
        __syncwarp();

        // ---- mean update + publish m_u pairs
        mloc = fmaf(k0, r0, fmaf(k1, r1, fmaf(k2, r2, fmaf(k3, r3, mloc))));
        muF[lane] = mloc;

        // ---- covariance downdate: p[i] -= z_i . z_lane (bitwise symmetric)
#pragma unroll
        for (int i = 0; i < Sn; ++i) {
            float4 zi = *(const float4*)&sZ[i * 4];
            float d = zi.x * z0;
            d = fmaf(zi.y, z1, d);
            d = fmaf(zi.z, z2, d);
            d = fmaf(zi.w, z3, d);
            p[i] -= d;
        }

        // ---- GEMM-A: X row `lane` = p . F^T  (F broadcasts; scalar stores)
        u64 x2[16];
#pragma unroll
        for (int c = 0; c < 16; ++c) x2[c] = 0ull;
#pragma unroll
        for (int l = 0; l < Sn; ++l) {
            u64 ps = pack2(p[l], p[l]);
            const ulonglong2* fr = (const ulonglong2*)&sFTp[l * 18];
#pragma unroll
            for (int c2 = 0; c2 < 8; ++c2) {
                ulonglong2 f = fr[c2];
                x2[2 * c2 + 0] = ffma2(ps, f.x, x2[2 * c2 + 0]);
                x2[2 * c2 + 1] = ffma2(ps, f.y, x2[2 * c2 + 1]);
            }
        }
#pragma unroll
        for (int c = 0; c < 16; ++c) {
            float xlo, xhi; unpack2(x2[c], xlo, xhi);
            sX[lane * XS + 2 * c + 0] = xlo;
            sX[lane * XS + 2 * c + 1] = xhi;
        }
        __syncwarp();

        // ---- mean predict: mp[lane] = sum_l F[lane][l]*m_u[l]
        //      scalar conflict-free F loads + pair broadcasts of m_u
        float mp;
        {
            u64 acc0 = 0ull, acc1 = 0ull;
            const float* frw = &sFRs[lane * XS];
#pragma unroll
            for (int c = 0; c < 8; ++c) {
                u64 fp0 = pack2(frw[4 * c + 0], frw[4 * c + 1]);
                u64 fp1 = pack2(frw[4 * c + 2], frw[4 * c + 3]);
                acc0 = ffma2(fp0, sMu[2 * c + 0], acc0);
                acc1 = ffma2(fp1, sMu[2 * c + 1], acc1);
            }
            u64 acc = fadd2(acc0, acc1);
            float alo, ahi; unpack2(acc, alo, ahi);
            mp = alo + ahi;
        }

        // ---- GEMM-B: P' col `lane` = F * X[:,lane] + Q[:,lane] (Q from regs)
        u64 a2[16];
#pragma unroll
        for (int c = 0; c < 16; ++c) a2[c] = q2[c];
#pragma unroll 8
        for (int k = 0; k < Sn; ++k) {
            float xv = sX[k * XS + lane];
            u64 xs = pack2(xv, xv);
            const ulonglong2* fr = (const ulonglong2*)&sFTp[k * 18];
#pragma unroll
            for (int c2 = 0; c2 < 8; ++c2) {
                ulonglong2 f = fr[c2];
                a2[2 * c2 + 0] = ffma2(xs, f.x, a2[2 * c2 + 0]);
                a2[2 * c2 + 1] = ffma2(xs, f.y, a2[2 * c2 + 1]);
            }
        }
#pragma unroll
        for (int c = 0; c < 16; ++c)
            unpack2(a2[c], p[2 * c], p[2 * c + 1]);

        mloc = mp;
        mpF[lane] = mp;
        __syncwarp();
    }
}

extern "C" void kernel_launch(void* const* d_in, const int* in_sizes, int n_in,
                              void* d_out, int out_size)
{
    const float* obs       = (const float*)d_in[0];
    const float* Fm        = (const float*)d_in[1];
    const float* Qm        = (const float*)d_in[2];
    const float* Hm        = (const float*)d_in[3];
    const float* Rm        = (const float*)d_in[4];
    const float* init_mean = (const float*)d_in[5];
    const float* init_cov  = (const float*)d_in[6];
    float* out = (float*)d_out;

    kalman_kernel<<<Bn, 32>>>(obs, Fm, Qm, Hm, Rm, init_mean, init_cov, out);
}

// round 11
// speedup vs baseline: 1.9764x; 1.5248x over previous
#include <cuda_runtime.h>
#include <math.h>
#include <stdint.h>

// Kalman filter one-step-ahead predictions. B=512, T=256, S=32, M=4.
// Warp-per-batch. Innovation path (PH^T, S, 4x4 Cholesky, z, downdate, means)
// = proven R7 FFMA code on a per-lane P column. The two 32x32 GEMMs run on the
// TENSOR pipe via mma.sync.m16n8k8 tf32 with 3-term splits:
//   X^T = F * P_u   (P symmetric)      P' = F * X + Q
// Both are left-multiplies by F -> one set of constant F A-fragments (hi+lo)
// held in registers for the whole kernel. Shared planes use stride 37 so all
// MMA-section LDS/STS are bank-conflict-free (5t+g / 5g+t injective mod 32).

#define Bn 512
#define Tn 256
#define Sn 32
#define Mn 4
#define PL 37   // fp32 plane stride: conflict-free row walks + frag reads

using u64 = unsigned long long;

__device__ __forceinline__ u64 pack2(float lo, float hi) {
    u64 r; asm("mov.b64 %0,{%1,%2};" : "=l"(r) : "f"(lo), "f"(hi)); return r;
}
__device__ __forceinline__ void unpack2(u64 v, float& lo, float& hi) {
    asm("mov.b64 {%0,%1},%2;" : "=f"(lo), "=f"(hi) : "l"(v));
}
__device__ __forceinline__ u64 ffma2(u64 a, u64 b, u64 c) {
    u64 d; asm("fma.rn.f32x2 %0,%1,%2,%3;" : "=l"(d) : "l"(a), "l"(b), "l"(c)); return d;
}
__device__ __forceinline__ u64 fadd2(u64 a, u64 b) {
    u64 d; asm("add.rn.f32x2 %0,%1,%2;" : "=l"(d) : "l"(a), "l"(b)); return d;
}
__device__ __forceinline__ uint32_t tf32hi(float x) {
    uint32_t r; asm("cvt.rna.tf32.f32 %0,%1;" : "=r"(r) : "f"(x)); return r;
}
__device__ __forceinline__ void mma_tf32(float* c, const uint32_t* a,
                                         uint32_t b0, uint32_t b1) {
    asm volatile(
        "mma.sync.aligned.m16n8k8.row.col.f32.tf32.tf32.f32 "
        "{%0,%1,%2,%3},{%4,%5,%6,%7},{%8,%9},{%0,%1,%2,%3};"
        : "+f"(c[0]), "+f"(c[1]), "+f"(c[2]), "+f"(c[3])
        : "r"(a[0]), "r"(a[1]), "r"(a[2]), "r"(a[3]), "r"(b0), "r"(b1));
}

__global__ __launch_bounds__(32) void kalman_kernel(
    const float* __restrict__ obs,       // [B,T,M]
    const float* __restrict__ Fm,        // [S,S]
    const float* __restrict__ Qm,        // [S,S]
    const float* __restrict__ Hm,        // [M,S]
    const float* __restrict__ Rm,        // [M,M]
    const float* __restrict__ init_mean, // [B,S]
    const float* __restrict__ init_cov,  // [B,S,S]
    float* __restrict__ out)
{
    const int b    = blockIdx.x;
    const int lane = threadIdx.x;
    const int g    = lane >> 2;   // groupID
    const int tg   = lane & 3;    // thread-in-group

    // H per-l quads: [l*4+q] = H[q][l]  (PH^T GEMM broadcasts)
    __shared__ __align__(16) u64 sHTp[Sn * 2];
    // H row-major pairs: hr[q*34+l] = H[q][l]  (mm & S dots)
    __shared__ __align__(16) u64 sHR[4 * 17];
    // F row-major pairs: fr[j*34+l] = F[j][l]  (mean predict)
    __shared__ __align__(16) u64 sFR[Sn * 17];
    // PH^T row-major pairs: pht[r*34+l] = (P H^T)[l][r]
    __shared__ __align__(16) u64 sPHT[4 * 17];
    // whitened z per row
    __shared__ __align__(16) float sZ[Sn * 4];
    // mean pair buffers
    __shared__ __align__(16) u64 sMu[16];
    __shared__ __align__(16) u64 sMp[16];
    __shared__ float sR16[16];
    // Q in MMA-accumulator fragment order: sQf[c*33 + lane]
    __shared__ float sQf[32 * 33];
    // fp32 planes (stride 37): P_u / P' plane, and X^T plane
    __shared__ float sPu[Sn * PL];
    __shared__ float sXt[Sn * PL];

    {
        float* frf = (float*)sFR;
        for (int idx = lane; idx < Sn * Sn; idx += 32) {
            int i = idx >> 5, l = idx & 31;
            frf[i * 34 + l] = Fm[idx];
        }
        float* hv  = (float*)sHTp;
        float* hrf = (float*)sHR;
        for (int idx = lane; idx < Mn * Sn; idx += 32) {
            int q = idx >> 5, l = idx & 31;
            float h = Hm[idx];
            hv [l * 4 + q]  = h;
            hrf[q * 34 + l] = h;
        }
        if (lane < 16) sR16[lane] = Rm[lane];
        // Q accumulator-layout fragments: tile ti = mt*4+nt, regs j=0..3
        for (int ti = 0; ti < 8; ++ti) {
            int mt = ti >> 2, nt = ti & 3;
#pragma unroll
            for (int j = 0; j < 4; ++j) {
                int row = mt * 16 + g + 8 * (j >> 1);
                int col = nt * 8 + 2 * tg + (j & 1);
                sQf[(ti * 4 + j) * 33 + lane] = Qm[row * Sn + col];
            }
        }
    }

    // ---- constant F A-fragments (m16n8k8 row-major), hi+lo tf32 split ----
    uint32_t fh[8][4], fl[8][4];   // [mt*4+kt][reg]
#pragma unroll
    for (int mt = 0; mt < 2; ++mt)
#pragma unroll
        for (int kt = 0; kt < 4; ++kt) {
            int r0 = mt * 16 + g, c0 = kt * 8 + tg;
            float v[4];
            v[0] = Fm[r0 * Sn + c0];
            v[1] = Fm[(r0 + 8) * Sn + c0];
            v[2] = Fm[r0 * Sn + c0 + 4];
            v[3] = Fm[(r0 + 8) * Sn + c0 + 4];
#pragma unroll
            for (int j = 0; j < 4; ++j) {
                uint32_t h = tf32hi(v[j]);
                fh[mt * 4 + kt][j] = h;
                fl[mt * 4 + kt][j] = tf32hi(v[j] - __uint_as_float(h));
            }
        }

    // per-lane state: P column `lane` (== row, symmetric), mean element
    float p[Sn];
#pragma unroll
    for (int i = 0; i < Sn; ++i)
        p[i] = init_cov[(size_t)b * (Sn * Sn) + i * Sn + lane];
    float mloc = init_mean[b * Sn + lane];

    float* muF = (float*)sMu;
    float* mpF = (float*)sMp;
    mpF[lane] = mloc;
    __syncwarp();

    const float* yb = obs + (size_t)b * (Tn * Mn);
    float* out_means = out;
    float* out_covs  = out + (size_t)Tn * Bn * Mn;

    float4 yn = *(const float4*)yb;
    float* phtF = (float*)sPHT;

#pragma unroll 1
    for (int t = 0; t < Tn; ++t) {
        float4 yv = yn;
        int tnext = (t + 1 < Tn) ? (t + 1) : (Tn - 1);
        yn = *(const float4*)(yb + 4 * tnext);

        // ---- mm[q] on lane q (q<4): dot(H row q, m_p)
        float mmv = 0.f;
        {
            u64 accm0 = 0ull, accm1 = 0ull;
            const u64* hq = &sHR[(lane & 3) * 17];
#pragma unroll
            for (int c = 0; c < 8; ++c) {
                accm0 = ffma2(hq[2 * c + 0], sMp[2 * c + 0], accm0);
                accm1 = ffma2(hq[2 * c + 1], sMp[2 * c + 1], accm1);
            }
            u64 accm = fadd2(accm0, accm1);
            float alo, ahi; unpack2(accm, alo, ahi);
            mmv = alo + ahi;
        }

        // ---- phtt = row `lane` of P*H^T (4 split chains)
        u64 a00 = 0ull, a01 = 0ull, a10 = 0ull, a11 = 0ull;
#pragma unroll
        for (int l = 0; l < Sn; l += 2) {
            ulonglong2 h0 = *(const ulonglong2*)&sHTp[l * 2];
            ulonglong2 h1 = *(const ulonglong2*)&sHTp[(l + 1) * 2];
            u64 ps0 = pack2(p[l], p[l]);
            u64 ps1 = pack2(p[l + 1], p[l + 1]);
            a00 = ffma2(ps0, h0.x, a00); a10 = ffma2(ps0, h0.y, a10);
            a01 = ffma2(ps1, h1.x, a01); a11 = ffma2(ps1, h1.y, a11);
        }
        u64 ph2a = fadd2(a00, a01);
        u64 ph2b = fadd2(a10, a11);
        float ph0, ph1, phh2, ph3;
        unpack2(ph2a, ph0, ph1);
        unpack2(ph2b, phh2, ph3);
        phtF[0 * 34 + lane] = ph0;
        phtF[1 * 34 + lane] = ph1;
        phtF[2 * 34 + lane] = phh2;
        phtF[3 * 34 + lane] = ph3;

        float c0 = __shfl_sync(0xffffffffu, mmv, 0);
        float c1 = __shfl_sync(0xffffffffu, mmv, 1);
        float c2 = __shfl_sync(0xffffffffu, mmv, 2);
        float c3 = __shfl_sync(0xffffffffu, mmv, 3);
        if (lane == 0)
            *(float4*)&out_means[((size_t)t * Bn + b) * 4] = make_float4(c0, c1, c2, c3);
        float r0 = yv.x - c0, r1 = yv.y - c1, r2 = yv.z - c2, r3 = yv.w - c3;
        __syncwarp();

        // ---- S = H*(PH^T) + R
        int q = (lane >> 2) & 3, r = lane & 3;
        float sv;
        {
            u64 acc0 = 0ull, acc1 = 0ull;
            const u64* hq = &sHR [q * 17];
            const u64* pr = &sPHT[r * 17];
#pragma unroll
            for (int c = 0; c < 8; ++c) {
                acc0 = ffma2(hq[2 * c + 0], pr[2 * c + 0], acc0);
                acc1 = ffma2(hq[2 * c + 1], pr[2 * c + 1], acc1);
            }
            u64 acc = fadd2(acc0, acc1);
            float alo, ahi; unpack2(acc, alo, ahi);
            sv = sR16[(q << 2) | r] + (alo + ahi);
        }
        if (lane < 16)
            out_covs[((size_t)t * Bn + b) * 16 + lane] = sv;

        if (t == Tn - 1) break;

        // ---- broadcast S, rsqrt 4x4 Cholesky (redundant per lane)
        float s00 = __shfl_sync(0xffffffffu, sv, 0);
        float s10 = __shfl_sync(0xffffffffu, sv, 4);
        float s11 = __shfl_sync(0xffffffffu, sv, 5);
        float s20 = __shfl_sync(0xffffffffu, sv, 8);
        float s21 = __shfl_sync(0xffffffffu, sv, 9);
        float s22 = __shfl_sync(0xffffffffu, sv, 10);
        float s30 = __shfl_sync(0xffffffffu, sv, 12);
        float s31 = __shfl_sync(0xffffffffu, sv, 13);
        float s32 = __shfl_sync(0xffffffffu, sv, 14);
        float s33 = __shfl_sync(0xffffffffu, sv, 15);
        float i0 = rsqrtf(s00);
        float L10 = s10 * i0, L20 = s20 * i0, L30 = s30 * i0;
        float i1 = rsqrtf(s11 - L10 * L10);
        float L21 = (s21 - L20 * L10) * i1;
        float L31 = (s31 - L30 * L10) * i1;
        float i2 = rsqrtf(s22 - L20 * L20 - L21 * L21);
        float L32 = (s32 - L30 * L20 - L31 * L21) * i2;
        float i3 = rsqrtf(s33 - L30 * L30 - L31 * L31 - L32 * L32);

        float z0 = ph0 * i0;
        float z1 = (ph1 - L10 * z0) * i1;
        float z2 = (phh2 - L20 * z0 - L21 * z1) * i2;
        float z3 = (ph3 - L30 * z0 - L31 * z1 - L32 * z2) * i3;
        float k3 = z3 * i3;
        float k2 = (z2 - L32 * k3) * i2;
        float k1 = (z1 - L21 * k2 - L31 * k3) * i1;
        float k0 = (z0 - L10 * k1 - L20 * k2 - L30 * k3) * i0;

        *(float4*)&sZ[lane * 4] = make_float4(z0, z1, z2, z3);
        __syncwarp();

        mloc = fmaf(k0, r0, fmaf(k1, r1, fmaf(k2, r2, fmaf(k3, r3, mloc))));
        muF[lane] = mloc;

        // ---- symmetric rank-4 downdate (bitwise symmetric)
#pragma unroll
        for (int i = 0; i < Sn; ++i) {
            float4 zi = *(const float4*)&sZ[i * 4];
            float d = zi.x * z0;
            d = fmaf(zi.y, z1, d);
            d = fmaf(zi.z, z2, d);
            d = fmaf(zi.w, z3, d);
            p[i] -= d;
        }

        // ---- publish P_u plane: sPu[i*37 + lane] = P_u[i][lane] (cf)
#pragma unroll
        for (int i = 0; i < Sn; ++i)
            sPu[i * PL + lane] = p[i];
        __syncwarp();

        // ---- MMA1: X^T = F * P_u  (acc layout), 3-term tf32
        float xac[8][4];
#pragma unroll
        for (int ti = 0; ti < 8; ++ti)
#pragma unroll
            for (int j = 0; j < 4; ++j) xac[ti][j] = 0.f;
#pragma unroll
        for (int kt = 0; kt < 4; ++kt) {
#pragma unroll
            for (int nt = 0; nt < 4; ++nt) {
                float rb0 = sPu[(kt * 8 + tg) * PL + nt * 8 + g];
                float rb1 = sPu[(kt * 8 + tg + 4) * PL + nt * 8 + g];
                uint32_t bh0 = tf32hi(rb0);
                uint32_t bh1 = tf32hi(rb1);
                uint32_t bl0 = tf32hi(rb0 - __uint_as_float(bh0));
                uint32_t bl1 = tf32hi(rb1 - __uint_as_float(bh1));
#pragma unroll
                for (int mt = 0; mt < 2; ++mt) {
                    mma_tf32(xac[mt * 4 + nt], fh[mt * 4 + kt], bh0, bh1);
                    mma_tf32(xac[mt * 4 + nt], fh[mt * 4 + kt], bl0, bl1);
                    mma_tf32(xac[mt * 4 + nt], fl[mt * 4 + kt], bh0, bh1);
                }
            }
        }
        // store X^T plane (conflict-free)
#pragma unroll
        for (int ti = 0; ti < 8; ++ti) {
            int mt = ti >> 2, nt = ti & 3;
            int rr = mt * 16 + g, cc = nt * 8 + 2 * tg;
            sXt[rr * PL + cc]           = xac[ti][0];
            sXt[rr * PL + cc + 1]       = xac[ti][1];
            sXt[(rr + 8) * PL + cc]     = xac[ti][2];
            sXt[(rr + 8) * PL + cc + 1] = xac[ti][3];
        }
        __syncwarp();

        // ---- mean predict: mp[lane] = sum_l F[lane][l]*m_u[l]
        float mp;
        {
            u64 acc0 = 0ull, acc1 = 0ull;
            const u64* frw = &sFR[lane * 17];
#pragma unroll
            for (int c = 0; c < 8; ++c) {
                acc0 = ffma2(frw[2 * c + 0], sMu[2 * c + 0], acc0);
                acc1 = ffma2(frw[2 * c + 1], sMu[2 * c + 1], acc1);
            }
            u64 acc = fadd2(acc0, acc1);
            float alo, ahi; unpack2(acc, alo, ahi);
            mp = alo + ahi;
        }

        // ---- MMA2: P' = F * X + Q ; acc init from Q fragments
        float pac[8][4];
#pragma unroll
        for (int ti = 0; ti < 8; ++ti)
#pragma unroll
            for (int j = 0; j < 4; ++j)
                pac[ti][j] = sQf[(ti * 4 + j) * 33 + lane];
#pragma unroll
        for (int kt = 0; kt < 4; ++kt) {
#pragma unroll
            for (int nt = 0; nt < 4; ++nt) {
                // B = X: X[k][n] = X^T[n][k] -> transposed read (conflict-free)
                float rb0 = sXt[(nt * 8 + g) * PL + kt * 8 + tg];
                float rb1 = sXt[(nt * 8 + g) * PL + kt * 8 + tg + 4];
                uint32_t bh0 = tf32hi(rb0);
                uint32_t bh1 = tf32hi(rb1);
                uint32_t bl0 = tf32hi(rb0 - __uint_as_float(bh0));
                uint32_t bl1 = tf32hi(rb1 - __uint_as_float(bh1));
#pragma unroll
                for (int mt = 0; mt < 2; ++mt) {
                    mma_tf32(pac[mt * 4 + nt], fh[mt * 4 + kt], bh0, bh1);
                    mma_tf32(pac[mt * 4 + nt], fh[mt * 4 + kt], bl0, bl1);
                    mma_tf32(pac[mt * 4 + nt], fl[mt * 4 + kt], bh0, bh1);
                }
            }
        }
        // store P' plane (reuse sPu; P_u fully consumed)
#pragma unroll
        for (int ti = 0; ti < 8; ++ti) {
            int mt = ti >> 2, nt = ti & 3;
            int rr = mt * 16 + g, cc = nt * 8 + 2 * tg;
            sPu[rr * PL + cc]           = pac[ti][0];
            sPu[rr * PL + cc + 1]       = pac[ti][1];
            sPu[(rr + 8) * PL + cc]     = pac[ti][2];
            sPu[(rr + 8) * PL + cc + 1] = pac[ti][3];
        }
        __syncwarp();

        // ---- reload per-lane column of P' (conflict-free)
#pragma unroll
        for (int i = 0; i < Sn; ++i)
            p[i] = sPu[i * PL + lane];

        mloc = mp;
        mpF[lane] = mp;
        __syncwarp();
    }
}

extern "C" void kernel_launch(void* const* d_in, const int* in_sizes, int n_in,
                              void* d_out, int out_size)
{
    const float* obs       = (const float*)d_in[0];
    const float* Fm        = (const float*)d_in[1];
    const float* Qm        = (const float*)d_in[2];
    const float* Hm        = (const float*)d_in[3];
    const float* Rm        = (const float*)d_in[4];
    const float* init_mean = (const float*)d_in[5];
    const float* init_cov  = (const float*)d_in[6];
    float* out = (float*)d_out;

    kalman_kernel<<<Bn, 32>>>(obs, Fm, Qm, Hm, Rm, init_mean, init_cov, out);
}